// round 10
// baseline (speedup 1.0000x reference)
#include <cuda_runtime.h>

#define HID 64
#define G3  192     // 3*H
#define BB  512
#define TT  1024
#define GEMM_ROWS 128

// ---------------- scratch (device globals; no allocations) ----------------
__device__ float g_xg[(size_t)BB * TT * G3];   // 402 MB
__device__ float g_hA[(size_t)BB * TT * HID];  // 134 MB
__device__ float g_hB[(size_t)BB * TT * HID];  // 134 MB

typedef unsigned long long u64;

__device__ __forceinline__ void ffma2(u64& acc, u64 a, u64 b) {
    asm("fma.rn.f32x2 %0, %1, %2, %0;" : "+l"(acc) : "l"(a), "l"(b));
}
__device__ __forceinline__ float hsum2(u64 v) {
    float lo, hi;
    asm("mov.b64 {%0, %1}, %2;" : "=f"(lo), "=f"(hi) : "l"(v));
    return lo + hi;
}

// HW tanh (MUFU.TANH): lat ~16. Verified rel_err 2.6e-6 at final output.
__device__ __forceinline__ float htanh(float x) {
    float y;
    asm("tanh.approx.f32 %0, %1;" : "=f"(y) : "f"(x));
    return y;
}
__device__ __forceinline__ float hsig(float x) {
    return fmaf(0.5f, htanh(0.5f * x), 0.5f);
}

// ---------------- layer-0 input pre-activations (K=5, memory bound) -------
__global__ __launch_bounds__(192) void xg0_kernel(
    const float* __restrict__ x, const float* __restrict__ w,
    const float* __restrict__ b)
{
    __shared__ float ws[G3 * 5];
    __shared__ float bs[G3];
    __shared__ float xs[8][5];
    int g = threadIdx.x;                  // 0..191
    for (int i = g; i < G3 * 5; i += 192) ws[i] = w[i];
    if (g < G3) bs[g] = b[g];
    size_t row0 = (size_t)blockIdx.x * 8;
    if (g < 40) xs[g / 5][g % 5] = x[row0 * 5 + g];
    __syncthreads();
#pragma unroll
    for (int r = 0; r < 8; r++) {
        float acc = bs[g];
#pragma unroll
        for (int i = 0; i < 5; i++) acc += xs[r][i] * ws[g * 5 + i];
        g_xg[(row0 + r) * G3 + g] = acc;
    }
}

// ---------------- xg GEMM for layers 1..4: [BT,64]x[64,192]+b -------------
__global__ void __launch_bounds__(192, 2) xg_gemm_kernel(
    int insel, const float* __restrict__ w, const float* __restrict__ bias)
{
    const float* __restrict__ hin = insel ? g_hB : g_hA;
    __shared__ __align__(16) float hs[GEMM_ROWS][HID];  // 32 KB
    int t  = threadIdx.x;
    int g  = t % 96;                      // column-pair base
    int rh = t / 96;                      // row half

    u64 w0[32], w1[32];
    const ulonglong2* p0 = (const ulonglong2*)&w[(size_t)g * HID];
    const ulonglong2* p1 = (const ulonglong2*)&w[(size_t)(g + 96) * HID];
#pragma unroll
    for (int q = 0; q < 16; q++) {
        ulonglong2 a = p0[q]; w0[2 * q] = a.x; w0[2 * q + 1] = a.y;
        ulonglong2 c = p1[q]; w1[2 * q] = c.x; w1[2 * q + 1] = c.y;
    }
    float b0 = bias[g], b1 = bias[g + 96];

    size_t row0 = (size_t)blockIdx.x * GEMM_ROWS;
    const float4* src = (const float4*)&hin[row0 * HID];
    float4* dst = (float4*)&hs[0][0];
    for (int i = t; i < GEMM_ROWS * HID / 4; i += 192) dst[i] = src[i];
    __syncthreads();

    float* outp = &g_xg[(row0 + (size_t)rh * 64) * G3];
#pragma unroll 1
    for (int r = 0; r < 64; r++) {
        u64 a0 = 0, a1 = 0, c0 = 0, c1 = 0;
        const ulonglong2* hrow = (const ulonglong2*)&hs[rh * 64 + r][0];
#pragma unroll
        for (int q = 0; q < 16; q++) {
            ulonglong2 hv = hrow[q];            // LDS.128 broadcast per warp
            ffma2(a0, w0[2 * q], hv.x);
            ffma2(a1, w0[2 * q + 1], hv.y);
            ffma2(c0, w1[2 * q], hv.x);
            ffma2(c1, w1[2 * q + 1], hv.y);
        }
        outp[r * G3 + g]      = b0 + hsum2(a0) + hsum2(a1);
        outp[r * G3 + g + 96] = b1 + hsum2(c0) + hsum2(c1);
    }
}

// ---------------- recurrence: 2 batch rows software-pipelined per group ---
// CTA = 128 thr = 2 groups x 64 thr; each group owns rows A,B sharing the
// same weight registers. Per step: matvecA; matvecB; gatesA; STS; bar;
// gatesB; STS; bar  -> each row's serial tail (gates/STS/bar/LDS) hides
// under the other row's 192-cycle FMA stream. 1 warp/SMSP, pure static ILP.
template<bool WRITE_ALL>
__global__ void __launch_bounds__(128, 1) rec_kernel(
    const float* __restrict__ whh, const float* __restrict__ bhh, int outsel)
{
    float* __restrict__ hout = outsel ? g_hB : g_hA;
    __shared__ __align__(16) float hbuf[2][4][HID];   // [phase][CTA row][j]

    int tid = threadIdx.x;
    int grp = tid >> 6;                   // 0..1
    int j   = tid & 63;                   // hidden unit
    int ra  = grp * 2, rb = ra + 1;       // CTA-local row slots
    int bA  = blockIdx.x * 4 + ra;        // global batch rows
    int bB  = bA + 1;
    int barid = grp + 1;

    // weights: rows j (r), 64+j (z), 128+j (n), packed pairs in u64
    u64 wr[32], wz[32], wn[32];
    {
        const ulonglong2* rr = (const ulonglong2*)&whh[(size_t)j * HID];
        const ulonglong2* rz = (const ulonglong2*)&whh[(size_t)(HID + j) * HID];
        const ulonglong2* rn = (const ulonglong2*)&whh[(size_t)(2 * HID + j) * HID];
#pragma unroll
        for (int q = 0; q < 16; q++) {
            ulonglong2 a = rr[q]; wr[2 * q] = a.x; wr[2 * q + 1] = a.y;
            ulonglong2 c = rz[q]; wz[2 * q] = c.x; wz[2 * q + 1] = c.y;
            ulonglong2 d = rn[q]; wn[2 * q] = d.x; wn[2 * q + 1] = d.y;
        }
    }
    float br = bhh[j], bz = bhh[HID + j], bn = bhh[2 * HID + j];

    hbuf[0][ra][j] = 0.0f;
    hbuf[0][rb][j] = 0.0f;
    float hpA = 0.0f, hpB = 0.0f;

    const float* xgA = &g_xg[(size_t)bA * TT * G3];
    const float* xgB = &g_xg[(size_t)bB * TT * G3];
    float xrA = xgA[j], xzA = xgA[HID + j], xnA = xgA[2 * HID + j];
    float xrB = xgB[j], xzB = xgB[HID + j], xnB = xgB[2 * HID + j];
    float* opA = hout + (size_t)bA * TT * HID;
    float* opB = hout + (size_t)bB * TT * HID;

    __syncthreads();

    int p = 0;
    for (int t = 0; t < TT; t++) {
        // prefetch xg for t+1 (both rows)
        float xrA_n = 0.f, xzA_n = 0.f, xnA_n = 0.f;
        float xrB_n = 0.f, xzB_n = 0.f, xnB_n = 0.f;
        if (t + 1 < TT) {
            const float* qa = xgA + (size_t)(t + 1) * G3;
            const float* qb = xgB + (size_t)(t + 1) * G3;
            xrA_n = qa[j]; xzA_n = qa[HID + j]; xnA_n = qa[2 * HID + j];
            xrB_n = qb[j]; xzB_n = qb[HID + j]; xnB_n = qb[2 * HID + j];
        }

        // ---- matvec A ----
        u64 arA = 0, ar1A = 0, azA = 0, az1A = 0, anA = 0, an1A = 0;
        {
            const ulonglong2* hrow = (const ulonglong2*)&hbuf[p][ra][0];
#pragma unroll
            for (int q = 0; q < 16; q++) {
                ulonglong2 hv = hrow[q];          // LDS.128 broadcast
                ffma2(arA, wr[2 * q], hv.x); ffma2(ar1A, wr[2 * q + 1], hv.y);
                ffma2(azA, wz[2 * q], hv.x); ffma2(az1A, wz[2 * q + 1], hv.y);
                ffma2(anA, wn[2 * q], hv.x); ffma2(an1A, wn[2 * q + 1], hv.y);
            }
        }
        // ---- matvec B (independent; overlaps A's tail) ----
        u64 arB = 0, ar1B = 0, azB = 0, az1B = 0, anB = 0, an1B = 0;
        {
            const ulonglong2* hrow = (const ulonglong2*)&hbuf[p][rb][0];
#pragma unroll
            for (int q = 0; q < 16; q++) {
                ulonglong2 hv = hrow[q];
                ffma2(arB, wr[2 * q], hv.x); ffma2(ar1B, wr[2 * q + 1], hv.y);
                ffma2(azB, wz[2 * q], hv.x); ffma2(az1B, wz[2 * q + 1], hv.y);
                ffma2(anB, wn[2 * q], hv.x); ffma2(an1B, wn[2 * q + 1], hv.y);
            }
        }

        // ---- gates + commit A ----
        {
            float ghr = br + hsum2(arA) + hsum2(ar1A);
            float ghz = bz + hsum2(azA) + hsum2(az1A);
            float ghn = bn + hsum2(anA) + hsum2(an1A);
            float r  = hsig(xrA + ghr);
            float z  = hsig(xzA + ghz);
            float n  = htanh(xnA + r * ghn);
            float hn = n + z * (hpA - n);
            hpA = hn;
            hbuf[p ^ 1][ra][j] = hn;
            if (WRITE_ALL || t == TT - 1) opA[(size_t)t * HID + j] = hn;
        }
        asm volatile("bar.sync %0, 64;" :: "r"(barid) : "memory");

        // ---- gates + commit B (bar above drains under this work) ----
        {
            float ghr = br + hsum2(arB) + hsum2(ar1B);
            float ghz = bz + hsum2(azB) + hsum2(az1B);
            float ghn = bn + hsum2(anB) + hsum2(an1B);
            float r  = hsig(xrB + ghr);
            float z  = hsig(xzB + ghz);
            float n  = htanh(xnB + r * ghn);
            float hn = n + z * (hpB - n);
            hpB = hn;
            hbuf[p ^ 1][rb][j] = hn;
            if (WRITE_ALL || t == TT - 1) opB[(size_t)t * HID + j] = hn;
        }
        asm volatile("bar.sync %0, 64;" :: "r"(barid) : "memory");

        p ^= 1;
        xrA = xrA_n; xzA = xzA_n; xnA = xnA_n;
        xrB = xrB_n; xzB = xzB_n; xnB = xnB_n;
    }
}

// ---------------- final FC on last timestep -------------------------------
__global__ void fc_kernel(int insel, const float* __restrict__ wfc,
                          const float* __restrict__ bfc, float* __restrict__ out)
{
    const float* __restrict__ hin = insel ? g_hB : g_hA;
    int b = blockIdx.x;
    int j = threadIdx.x;                   // 64
    __shared__ float s[64];
    s[j] = hin[((size_t)b * TT + (TT - 1)) * HID + j] * wfc[j];
    __syncthreads();
    if (j < 32) {
        float a = s[j] + s[j + 32];
        for (int o = 16; o > 0; o >>= 1) a += __shfl_down_sync(0xffffffff, a, o);
        if (j == 0) out[b] = a + bfc[0];
    }
}

// ---------------- launch ---------------------------------------------------
extern "C" void kernel_launch(void* const* d_in, const int* in_sizes, int n_in,
                              void* d_out, int out_size)
{
    const float* x     = (const float*)d_in[0];
    const float* w_ih0 = (const float*)d_in[1];
    const float* w_hh0 = (const float*)d_in[2];
    const float* b_ih0 = (const float*)d_in[3];
    const float* b_hh0 = (const float*)d_in[4];
    const float* w_ih  = (const float*)d_in[5];
    const float* w_hh  = (const float*)d_in[6];
    const float* b_ih  = (const float*)d_in[7];
    const float* b_hh  = (const float*)d_in[8];
    const float* w_fc  = (const float*)d_in[9];
    const float* b_fc  = (const float*)d_in[10];
    float* out = (float*)d_out;

    // layer 0
    xg0_kernel<<<(BB * TT) / 8, 192>>>(x, w_ih0, b_ih0);
    rec_kernel<true><<<BB / 4, 128>>>(w_hh0, b_hh0, /*outsel=*/0);   // -> A

    // layers 1..4: xg GEMM then recurrence, ping-ponging A/B
    int insel = 0;
    for (int l = 0; l < 4; l++) {
        xg_gemm_kernel<<<(BB * TT) / GEMM_ROWS, 192>>>(
            insel, w_ih + (size_t)l * G3 * HID, b_ih + (size_t)l * G3);
        int outsel = insel ^ 1;
        if (l < 3)
            rec_kernel<true><<<BB / 4, 128>>>(
                w_hh + (size_t)l * G3 * HID, b_hh + (size_t)l * G3, outsel);
        else  // last layer: only t = TT-1 is consumed by fc
            rec_kernel<false><<<BB / 4, 128>>>(
                w_hh + (size_t)l * G3 * HID, b_hh + (size_t)l * G3, outsel);
        insel = outsel;
    }

    fc_kernel<<<BB, 64>>>(insel, w_fc, b_fc, out);
}

// round 17
// speedup vs baseline: 1.4849x; 1.4849x over previous
#include <cuda_runtime.h>
#include <cuda_bf16.h>
#include <cstdint>

#define HID 64
#define G3  192     // 3*H
#define BB  512
#define TT  1024

// ---------------- scratch (device globals; no allocations) ----------------
__device__ float g_xg[(size_t)BB * TT * G3];   // 402 MB
__device__ float g_hA[(size_t)BB * TT * HID];  // 134 MB
__device__ float g_hB[(size_t)BB * TT * HID];  // 134 MB

typedef unsigned long long u64;

__device__ __forceinline__ void ffma2(u64& acc, u64 a, u64 b) {
    asm("fma.rn.f32x2 %0, %1, %2, %0;" : "+l"(acc) : "l"(a), "l"(b));
}
__device__ __forceinline__ float hsum2(u64 v) {
    float lo, hi;
    asm("mov.b64 {%0, %1}, %2;" : "=f"(lo), "=f"(hi) : "l"(v));
    return lo + hi;
}
__device__ __forceinline__ float fsig(float x) {
    return __fdividef(1.0f, 1.0f + __expf(-x));
}
__device__ __forceinline__ float ftanh_fast(float x) {
    float e = __expf(-2.0f * x);
    return __fdividef(1.0f - e, 1.0f + e);
}

// ---------------- layer-0 input pre-activations (K=5, memory bound) -------
__global__ __launch_bounds__(192) void xg0_kernel(
    const float* __restrict__ x, const float* __restrict__ w,
    const float* __restrict__ b)
{
    __shared__ float ws[G3 * 5];
    __shared__ float bs[G3];
    __shared__ float xs[8][5];
    int g = threadIdx.x;
    for (int i = g; i < G3 * 5; i += 192) ws[i] = w[i];
    if (g < G3) bs[g] = b[g];
    size_t row0 = (size_t)blockIdx.x * 8;
    if (g < 40) xs[g / 5][g % 5] = x[row0 * 5 + g];
    __syncthreads();
#pragma unroll
    for (int r = 0; r < 8; r++) {
        float acc = bs[g];
#pragma unroll
        for (int i = 0; i < 5; i++) acc += xs[r][i] * ws[g * 5 + i];
        g_xg[(row0 + r) * G3 + g] = acc;
    }
}

// ====== xg GEMM on HMMA tensor cores: [BT,64]x[64,192]+b, bf16x3 ==========
// mma.sync.m16n8k16 (sm_80 baseline PTX; works on compute_103).
// CTA = 256 thr (8 warps), tile 128 rows x 192 cols. A,B as hi/lo bf16 in
// padded row-major smem (stride 72 bf16 = 144B: 16B-aligned rows, phase-
// shifted -> conflict-free ldmatrix). 3 passes: AhBh + AhBl + AlBh.
#define LDP 72                       // padded row stride in bf16
#define SM_AH 0                      // 128*72*2 = 18432
#define SM_AL 18432
#define SM_BH 36864                  // 192*72*2 = 27648
#define SM_BL 64512
#define SM_BI 92160                  // bias, 768 B
#define SMEM_TC 92928

__device__ __forceinline__ uint32_t smem_u32(const void* p) {
    uint32_t a;
    asm("{ .reg .u64 t; cvta.to.shared.u64 t, %1; cvt.u32.u64 %0, t; }"
        : "=r"(a) : "l"(p));
    return a;
}
__device__ __forceinline__ void ldsm_x4(uint32_t& r0, uint32_t& r1,
                                        uint32_t& r2, uint32_t& r3, uint32_t a) {
    asm volatile("ldmatrix.sync.aligned.m8n8.x4.shared.b16 {%0,%1,%2,%3}, [%4];"
                 : "=r"(r0), "=r"(r1), "=r"(r2), "=r"(r3) : "r"(a));
}
__device__ __forceinline__ void ldsm_x2(uint32_t& r0, uint32_t& r1, uint32_t a) {
    asm volatile("ldmatrix.sync.aligned.m8n8.x2.shared.b16 {%0,%1}, [%2];"
                 : "=r"(r0), "=r"(r1) : "r"(a));
}
__device__ __forceinline__ void mma_bf16(float* c, uint32_t a0, uint32_t a1,
                                         uint32_t a2, uint32_t a3,
                                         uint32_t b0, uint32_t b1) {
    asm volatile(
        "mma.sync.aligned.m16n8k16.row.col.f32.bf16.bf16.f32 "
        "{%0,%1,%2,%3}, {%4,%5,%6,%7}, {%8,%9}, {%0,%1,%2,%3};"
        : "+f"(c[0]), "+f"(c[1]), "+f"(c[2]), "+f"(c[3])
        : "r"(a0), "r"(a1), "r"(a2), "r"(a3), "r"(b0), "r"(b1));
}
__device__ __forceinline__ void split_store(char* base, int row, int kb, float4 v) {
    __nv_bfloat162 h01, h23;
    h01.x = __float2bfloat16(v.x); h01.y = __float2bfloat16(v.y);
    h23.x = __float2bfloat16(v.z); h23.y = __float2bfloat16(v.w);
    uint32_t off = (uint32_t)(row * LDP + kb) * 2;
    *(__nv_bfloat162*)(base + off)     = h01;
    *(__nv_bfloat162*)(base + off + 4) = h23;
}
__device__ __forceinline__ void split_store_lo(char* base, int row, int kb, float4 v) {
    __nv_bfloat162 l01, l23;
    l01.x = __float2bfloat16(v.x - __bfloat162float(__float2bfloat16(v.x)));
    l01.y = __float2bfloat16(v.y - __bfloat162float(__float2bfloat16(v.y)));
    l23.x = __float2bfloat16(v.z - __bfloat162float(__float2bfloat16(v.z)));
    l23.y = __float2bfloat16(v.w - __bfloat162float(__float2bfloat16(v.w)));
    uint32_t off = (uint32_t)(row * LDP + kb) * 2;
    *(__nv_bfloat162*)(base + off)     = l01;
    *(__nv_bfloat162*)(base + off + 4) = l23;
}

__global__ void __launch_bounds__(256) xg_tc_kernel(
    int insel, const float* __restrict__ w, const float* __restrict__ bias)
{
    extern __shared__ char smem[];
    const float* __restrict__ hin = insel ? g_hB : g_hA;
    uint32_t sb = smem_u32(smem);
    int tid = threadIdx.x, warp = tid >> 5, lane = tid & 31;
    size_t row0 = (size_t)blockIdx.x * 128;

    // bias -> smem
    for (int i = tid; i < G3; i += 256)
        ((float*)(smem + SM_BI))[i] = bias[i];

    // A: h tile [128,64] -> hi/lo bf16
    {
        const float4* src = (const float4*)(hin + row0 * HID);
        for (int q = tid; q < 2048; q += 256) {
            float4 v = src[q];
            int row = q >> 4, kb = (q & 15) * 4;
            split_store(smem + SM_AH, row, kb, v);
            split_store_lo(smem + SM_AL, row, kb, v);
        }
    }
    // B: w [192,64] -> hi/lo bf16
    {
        const float4* src = (const float4*)w;
        for (int q = tid; q < 3072; q += 256) {
            float4 v = src[q];
            int row = q >> 4, kb = (q & 15) * 4;
            split_store(smem + SM_BH, row, kb, v);
            split_store_lo(smem + SM_BL, row, kb, v);
        }
    }
    __syncthreads();

    float acc[24][4];
#pragma unroll
    for (int nt = 0; nt < 24; nt++)
#pragma unroll
        for (int i = 0; i < 4; i++) acc[nt][i] = 0.0f;

    // ldmatrix lane addressing
    int aRow = warp * 16 + (lane & 15);
    int aColH = (lane >> 4) * 8;
    int bRowL = lane & 7;
    int bColH = ((lane >> 3) & 1) * 8;

#pragma unroll
    for (int pass = 0; pass < 3; pass++) {
        uint32_t aBase = sb + ((pass == 2) ? SM_AL : SM_AH);
        uint32_t bBase = sb + ((pass == 1) ? SM_BL : SM_BH);
#pragma unroll
        for (int k = 0; k < 4; k++) {
            uint32_t a0, a1, a2, a3;
            ldsm_x4(a0, a1, a2, a3,
                    aBase + (uint32_t)(aRow * LDP + k * 16 + aColH) * 2);
#pragma unroll
            for (int nt = 0; nt < 24; nt++) {
                uint32_t b0, b1;
                ldsm_x2(b0, b1,
                        bBase + (uint32_t)((nt * 8 + bRowL) * LDP + k * 16 + bColH) * 2);
                mma_bf16(acc[nt], a0, a1, a2, a3, b0, b1);
            }
        }
    }

    // epilogue: c fragment rows lane/4, lane/4+8; cols (lane%4)*2
    int r0 = warp * 16 + (lane >> 2);
    int c0 = (lane & 3) * 2;
    float* out0 = &g_xg[(row0 + r0) * G3];
    float* out1 = &g_xg[(row0 + r0 + 8) * G3];
    const float* bp = (const float*)(smem + SM_BI);
#pragma unroll
    for (int nt = 0; nt < 24; nt++) {
        int c = nt * 8 + c0;
        float bx = bp[c], by = bp[c + 1];
        float2 v0 = make_float2(acc[nt][0] + bx, acc[nt][1] + by);
        float2 v1 = make_float2(acc[nt][2] + bx, acc[nt][3] + by);
        *(float2*)(out0 + c) = v0;
        *(float2*)(out1 + c) = v1;
    }
}

// ---------------- recurrence: R3-exact (measured best, 507us) -------------
__global__ void __launch_bounds__(256, 1) rec_kernel(
    const float* __restrict__ whh, const float* __restrict__ bhh,
    int outsel, int write_all)
{
    float* __restrict__ hout = outsel ? g_hB : g_hA;
    __shared__ __align__(16) float hbuf[2][4][HID];

    int tid = threadIdx.x;
    int grp = tid >> 6;
    int j   = tid & 63;
    int b   = blockIdx.x * 4 + grp;
    int barid = grp + 1;

    u64 wr[32], wz[32], wn[32];
    {
        const ulonglong2* rr = (const ulonglong2*)&whh[(size_t)j * HID];
        const ulonglong2* rz = (const ulonglong2*)&whh[(size_t)(HID + j) * HID];
        const ulonglong2* rn = (const ulonglong2*)&whh[(size_t)(2 * HID + j) * HID];
#pragma unroll
        for (int q = 0; q < 16; q++) {
            ulonglong2 a = rr[q]; wr[2 * q] = a.x; wr[2 * q + 1] = a.y;
            ulonglong2 c = rz[q]; wz[2 * q] = c.x; wz[2 * q + 1] = c.y;
            ulonglong2 d = rn[q]; wn[2 * q] = d.x; wn[2 * q + 1] = d.y;
        }
    }
    float br = bhh[j], bz = bhh[HID + j], bn = bhh[2 * HID + j];

    hbuf[0][grp][j] = 0.0f;
    float hprev = 0.0f;

    const float* xgp = &g_xg[(size_t)b * TT * G3];
    float xr = xgp[j], xz = xgp[HID + j], xn0 = xgp[2 * HID + j];

    asm volatile("bar.sync %0, 64;" :: "r"(barid) : "memory");

    int p = 0;
    for (int t = 0; t < TT; t++) {
        float xr_n = 0.f, xz_n = 0.f, xn_n = 0.f;
        if (t + 1 < TT) {
            const float* xq = xgp + (size_t)(t + 1) * G3;
            xr_n = xq[j]; xz_n = xq[HID + j]; xn_n = xq[2 * HID + j];
        }

        u64 ar0 = 0, ar1 = 0, az0 = 0, az1 = 0, an0 = 0, an1 = 0;
        const ulonglong2* hrow = (const ulonglong2*)&hbuf[p][grp][0];
#pragma unroll
        for (int q = 0; q < 16; q++) {
            ulonglong2 hv = hrow[q];
            ffma2(ar0, wr[2 * q], hv.x);
            ffma2(ar1, wr[2 * q + 1], hv.y);
            ffma2(az0, wz[2 * q], hv.x);
            ffma2(az1, wz[2 * q + 1], hv.y);
            ffma2(an0, wn[2 * q], hv.x);
            ffma2(an1, wn[2 * q + 1], hv.y);
        }
        float ghr = br + hsum2(ar0) + hsum2(ar1);
        float ghz = bz + hsum2(az0) + hsum2(az1);
        float ghn = bn + hsum2(an0) + hsum2(an1);

        float r  = fsig(xr + ghr);
        float z  = fsig(xz + ghz);
        float n  = ftanh_fast(xn0 + r * ghn);
        float hn = n + z * (hprev - n);

        hbuf[p ^ 1][grp][j] = hn;
        hprev = hn;
        if (write_all || t == TT - 1)
            hout[((size_t)b * TT + t) * HID + j] = hn;

        asm volatile("bar.sync %0, 64;" :: "r"(barid) : "memory");
        p ^= 1;
        xr = xr_n; xz = xz_n; xn0 = xn_n;
    }
}

// ---------------- final FC on last timestep -------------------------------
__global__ void fc_kernel(int insel, const float* __restrict__ wfc,
                          const float* __restrict__ bfc, float* __restrict__ out)
{
    const float* __restrict__ hin = insel ? g_hB : g_hA;
    int b = blockIdx.x;
    int j = threadIdx.x;
    __shared__ float s[64];
    s[j] = hin[((size_t)b * TT + (TT - 1)) * HID + j] * wfc[j];
    __syncthreads();
    if (j < 32) {
        float a = s[j] + s[j + 32];
        for (int o = 16; o > 0; o >>= 1) a += __shfl_down_sync(0xffffffff, a, o);
        if (j == 0) out[b] = a + bfc[0];
    }
}

// ---------------- launch ---------------------------------------------------
extern "C" void kernel_launch(void* const* d_in, const int* in_sizes, int n_in,
                              void* d_out, int out_size)
{
    const float* x     = (const float*)d_in[0];
    const float* w_ih0 = (const float*)d_in[1];
    const float* w_hh0 = (const float*)d_in[2];
    const float* b_ih0 = (const float*)d_in[3];
    const float* b_hh0 = (const float*)d_in[4];
    const float* w_ih  = (const float*)d_in[5];
    const float* w_hh  = (const float*)d_in[6];
    const float* b_ih  = (const float*)d_in[7];
    const float* b_hh  = (const float*)d_in[8];
    const float* w_fc  = (const float*)d_in[9];
    const float* b_fc  = (const float*)d_in[10];
    float* out = (float*)d_out;

    cudaFuncSetAttribute(xg_tc_kernel,
                         cudaFuncAttributeMaxDynamicSharedMemorySize, SMEM_TC);

    // layer 0
    xg0_kernel<<<(BB * TT) / 8, 192>>>(x, w_ih0, b_ih0);
    rec_kernel<<<BB / 4, 256>>>(w_hh0, b_hh0, /*outsel=*/0, /*write_all=*/1);

    // layers 1..4: HMMA xg GEMM then recurrence, ping-ponging A/B
    int insel = 0;
    for (int l = 0; l < 4; l++) {
        xg_tc_kernel<<<(BB * TT) / 128, 256, SMEM_TC>>>(
            insel, w_ih + (size_t)l * G3 * HID, b_ih + (size_t)l * G3);
        int outsel = insel ^ 1;
        int write_all = (l < 3) ? 1 : 0;
        rec_kernel<<<BB / 4, 256>>>(
            w_hh + (size_t)l * G3 * HID, b_hh + (size_t)l * G3, outsel, write_all);
        insel = outsel;
    }

    fc_kernel<<<BB, 64>>>(insel, w_fc, b_fc, out);
}